// round 14
// baseline (speedup 1.0000x reference)
#include <cuda_runtime.h>
#include <math.h>

// B=8, C=128, N=8192, K=9, PAD=4, DIL=1, STR=1, L=N
#define Bv 8
#define Cv 128
#define Nv 8192
#define Kv 9
#define HALF_K 4
#define TL 128           // l positions per block tile (kernel 2)
#define THREADS 256
#define CPB 32           // channels per block (kernel 2)
#define NITER (CPB / 8)  // 4 channel iterations

typedef unsigned long long ull;
union F2U { float2 f; ull u; };

__device__ __forceinline__ ull pk2(float lo, float hi) {
    F2U t; t.f = make_float2(lo, hi); return t.u;
}
__device__ __forceinline__ float lo2(ull v) { F2U t; t.u = v; return t.f.x; }
__device__ __forceinline__ float hi2(ull v) { F2U t; t.u = v; return t.f.y; }
__device__ __forceinline__ ull mul2(ull a, ull b) {
    ull d; asm("mul.rn.f32x2 %0, %1, %2;" : "=l"(d) : "l"(a), "l"(b)); return d;
}
__device__ __forceinline__ ull fma2(ull a, ull b, ull c) {
    ull d; asm("fma.rn.f32x2 %0, %1, %2, %3;" : "=l"(d) : "l"(a), "l"(b), "l"(c)); return d;
}

// Scratch: distance weights dwT[b][k][l] (2.36 MB) + duplicated conv weights
__device__ float g_dw[Bv * Kv * Nv];
__device__ ull   g_w2[Cv * Kv];

// ---------------- kernel 1: precompute dw + duplicated weights ----------------
__global__ __launch_bounds__(THREADS)
void dw_kernel(const float* __restrict__ coords,
               const float* __restrict__ sigma,
               const float* __restrict__ weight)
{
    const int b = blockIdx.y;
    const int l = blockIdx.x * THREADS + threadIdx.x;
    const float* cb = coords + b * 3 * Nv;
    const float inv_sig = 1.0f / sigma[0];

    const float cx = cb[l];
    const float cy = cb[Nv + l];
    const float cz = cb[2 * Nv + l];

    #pragma unroll
    for (int k = 0; k < Kv; k++) {
        const int idx = l + k - HALF_K;
        float dx, dy, dz;
        if (idx >= 0 && idx < Nv) {
            dx = cb[idx]          - cx;
            dy = cb[Nv + idx]     - cy;
            dz = cb[2 * Nv + idx] - cz;
        } else {
            dx = -cx; dy = -cy; dz = -cz;     // zero-padded coords
        }
        const float sq   = dx * dx + dy * dy + dz * dz;
        const float dist = (sq > 0.0f) ? sq * rsqrtf(sq) : 0.0f;  // == sqrt(sq)
        g_dw[(b * Kv + k) * Nv + l] = fmaxf(fmaf(-dist, inv_sig, 1.0f), 0.0f);
    }

    if (b == 0 && blockIdx.x == 0) {
        for (int i = threadIdx.x; i < Cv * Kv; i += THREADS) {
            const float w = weight[i];
            g_w2[i] = pk2(w, w);
        }
    }
}

// ---------------- kernel 2: pure streaming conv (no smem, no barriers) -------
__global__ __launch_bounds__(THREADS, 4)
void conv_kernel(const float* __restrict__ x,
                 float* __restrict__ out)
{
    const int b     = blockIdx.y;
    const int l0g   = blockIdx.x * TL;
    const int cbase = blockIdx.z * CPB;
    const int tid   = threadIdx.x;

    const int lane = tid & 31;
    const int w_id = tid >> 5;          // warp -> channel offset within pass
    const int lq   = lane * 4;          // local l of first output
    const int lg   = l0g + lq;          // global l

    // dq cache: 9 independent coalesced LDG.128 from precomputed dw (L2-hot)
    ull dqA[Kv], dqB[Kv];
    #pragma unroll
    for (int k = 0; k < Kv; k++) {
        const ulonglong2 dd = __ldg(reinterpret_cast<const ulonglong2*>(
                                        &g_dw[(b * Kv + k) * Nv + lg]));
        dqA[k] = dd.x;                  // (dw[l], dw[l+1])
        dqB[k] = dd.y;                  // (dw[l+2], dw[l+3])
    }

    const bool interior = (l0g >= HALF_K) && (l0g + TL + HALF_K <= Nv);

    if (interior) {
        const float* xb0 = x   + (b * Cv + cbase + w_id) * Nv + lg;  // stride 8*Nv
        float*       ob0 = out + (b * Cv + cbase + w_id) * Nv + lg;

        #pragma unroll
        for (int it = 0; it < NITER; ++it) {
            const float* xp = xb0 + it * 8 * Nv;
            const ulonglong2 A = *reinterpret_cast<const ulonglong2*>(xp - 4);
            const ulonglong2 M = *reinterpret_cast<const ulonglong2*>(xp);
            const ulonglong2 R = *reinterpret_cast<const ulonglong2*>(xp + 4);
            const ull P0 = A.x, P1 = A.y, P2 = M.x, P3 = M.y, P4 = R.x, P5 = R.y;
            const ull q0 = pk2(hi2(P0), lo2(P1));
            const ull q1 = pk2(hi2(P1), lo2(P2));
            const ull q2 = pk2(hi2(P2), lo2(P3));
            const ull q3 = pk2(hi2(P3), lo2(P4));
            const ull q4 = pk2(hi2(P4), lo2(P5));
            const ull xA[Kv] = { P0, q0, P1, q1, P2, q2, P3, q3, P4 };
            const ull xB[Kv] = { P1, q1, P2, q2, P3, q3, P4, q4, P5 };

            const ull* wc2 = &g_w2[(cbase + it * 8 + w_id) * Kv];
            ull accA = 0ull, accB = 0ull;
            #pragma unroll
            for (int k = 0; k < Kv; k++) {
                const ull w2 = __ldg(&wc2[k]);   // warp-uniform, L1 broadcast
                accA = fma2(mul2(xA[k], dqA[k]), w2, accA);
                accB = fma2(mul2(xB[k], dqB[k]), w2, accB);
            }
            F2U ra, rb; ra.u = accA; rb.u = accB;
            *reinterpret_cast<float4*>(ob0 + it * 8 * Nv) =
                make_float4(ra.f.x, ra.f.y, rb.f.x, rb.f.y);
        }
    } else {
        // boundary tiles (2 of 64 in l): guarded path
        #pragma unroll
        for (int it = 0; it < NITER; ++it) {
            const int c = cbase + it * 8 + w_id;
            const float* xb = x + (b * Cv + c) * Nv;
            float xv[12];
            #pragma unroll
            for (int j = 0; j < 12; j++) {
                const int idx = lg - HALF_K + j;
                xv[j] = (idx >= 0 && idx < Nv) ? xb[idx] : 0.0f;
            }
            const ull* wc2 = &g_w2[c * Kv];
            ull accA = 0ull, accB = 0ull;
            #pragma unroll
            for (int k = 0; k < Kv; k++) {
                const ull w2 = __ldg(&wc2[k]);
                accA = fma2(mul2(pk2(xv[k],     xv[k + 1]), dqA[k]), w2, accA);
                accB = fma2(mul2(pk2(xv[k + 2], xv[k + 3]), dqB[k]), w2, accB);
            }
            F2U ra, rb; ra.u = accA; rb.u = accB;
            *reinterpret_cast<float4*>(out + (b * Cv + c) * Nv + lg) =
                make_float4(ra.f.x, ra.f.y, rb.f.x, rb.f.y);
        }
    }
}

extern "C" void kernel_launch(void* const* d_in, const int* in_sizes, int n_in,
                              void* d_out, int out_size)
{
    const float* x      = (const float*)d_in[0];
    const float* coords = (const float*)d_in[1];
    const float* sigma  = (const float*)d_in[2];
    const float* weight = (const float*)d_in[3];
    float* out = (float*)d_out;

    dim3 g1(Nv / THREADS, Bv, 1);       // (32, 8): one thread per (b, l)
    dw_kernel<<<g1, THREADS>>>(coords, sigma, weight);

    dim3 g2(Nv / TL, Bv, Cv / CPB);     // (64, 8, 4) = 2048 blocks
    conv_kernel<<<g2, THREADS>>>(x, out);
}